// round 10
// baseline (speedup 1.0000x reference)
#include <cuda_runtime.h>
#include <cstdint>
#include <math.h>

#define BB 32
#define NN 256
#define HH 12
#define DD 64
#define CC 768

// ---------------- scratch (device globals; no runtime allocation) ----------------
__device__ float g_qin[BB*HH*NN*DD];      // (b,h,n,d)
__device__ float g_kin[BB*HH*NN*DD];      // (b,h,n,d)
__device__ float g_vt [BB*HH*DD*NN];      // (b,h,d,m)  V^T for PV GEMM
__device__ float g_qgr[BB*NN*CC];         // (b,n,h*64+d)
__device__ float g_kgr[BB*NN*CC];         // (b,n,h*64+d)
__device__ float g_sq [(size_t)BB*HH*NN*NN]; // gs*dots^2  (b,h,n,m)
__device__ float g_mix[(size_t)BB*HH*NN*NN]; // softmaxed P (b,o,n,m)
__device__ float g_ctx[BB*NN*CC];         // (b,n,h*64+d)

__device__ __forceinline__ float tf32_rna(float f) {
    uint32_t o;
    asm("cvt.rna.tf32.f32 %0, %1;" : "=r"(o) : "f"(f));
    return __uint_as_float(o);
}

__device__ __forceinline__ void mma_tf32(float* c, const float* a, const float* b) {
    asm volatile(
        "mma.sync.aligned.m16n8k8.row.col.f32.tf32.tf32.f32 "
        "{%0,%1,%2,%3}, {%4,%5,%6,%7}, {%8,%9}, {%0,%1,%2,%3};"
        : "+f"(c[0]), "+f"(c[1]), "+f"(c[2]), "+f"(c[3])
        : "r"(__float_as_uint(a[0])), "r"(__float_as_uint(a[1])),
          "r"(__float_as_uint(a[2])), "r"(__float_as_uint(a[3])),
          "r"(__float_as_uint(b[0])), "r"(__float_as_uint(b[1])));
}

// ======================= TF32 mma.sync GEMM (R3 structure — proven fast) =======================
// C[M,N] = A[M,K] @ B[N,K]^T. Block tile: 128 x TN, K-chunk 16.
// 8 warps 4(m) x 2(n); warp tile 32 x TN/2.
// MODE 0: qkv = x @ qkv_w^T + b, scatter to q/k/vt
// MODE 1: dots per (b,h); epilogue sq = gs*dots^2
// MODE 2: PV per (b,h): P(256x256) @ Vt(64x256)^T -> ctx
// MODE 3: proj = ctx @ proj_w^T + b -> out
template<int MODE, int TN, int NCH>
__global__ void __launch_bounds__(256) gemm_mma(const float* __restrict__ Ain,
                                                const float* __restrict__ Bin,
                                                const float* __restrict__ Xtra,
                                                float* __restrict__ Og)
{
    __shared__ float As[128 * 20];
    __shared__ float Bs[TN * 20];
    constexpr int NF = TN / 16;            // n-fragments per warp
    constexpr int NB4 = (TN * 4) / 256;    // B float4 loads per thread (2 or 1)

    const int tid = threadIdx.x, lane = tid & 31, wid = tid >> 5;
    const int wm = wid >> 1, wn = wid & 1;

    const float* Aba; const float* Bba; int sA, sB;
    if (MODE == 0) {
        Aba = Ain + (size_t)blockIdx.y * 128 * 768; sA = 768;
        Bba = Bin + (size_t)blockIdx.x * 128 * 768; sB = 768;
    } else if (MODE == 1) {
        int b = blockIdx.z, h = blockIdx.y;
        int nt = blockIdx.x >> 1, mt = blockIdx.x & 1;
        Aba = g_qgr + ((size_t)(b * 256 + nt * 128)) * 768 + h * 64; sA = 768;
        Bba = g_kgr + ((size_t)(b * 256 + mt * 128)) * 768 + h * 64; sB = 768;
    } else if (MODE == 2) {
        Aba = g_mix + (size_t)blockIdx.y * 65536 + (size_t)blockIdx.x * 128 * 256; sA = 256;
        Bba = g_vt + (size_t)blockIdx.y * 16384; sB = 256;
    } else {
        Aba = g_ctx + (size_t)blockIdx.y * 128 * 768; sA = 768;
        Bba = Bin + (size_t)blockIdx.x * 128 * 768; sB = 768;
    }

    float c[2][NF][4];
#pragma unroll
    for (int mf = 0; mf < 2; mf++)
#pragma unroll
        for (int nf = 0; nf < NF; nf++)
#pragma unroll
            for (int e = 0; e < 4; e++) c[mf][nf][e] = 0.f;

    float4 ra[2], rb[NB4];

    // prologue loads
#pragma unroll
    for (int i = 0; i < 2; i++) {
        int f = tid + i * 256; int r = f >> 2, cc = (f & 3) * 4;
        ra[i] = *(const float4*)(Aba + (size_t)r * sA + cc);
    }
#pragma unroll
    for (int i = 0; i < NB4; i++) {
        int f = tid + i * 256; int r = f >> 2, cc = (f & 3) * 4;
        rb[i] = *(const float4*)(Bba + (size_t)r * sB + cc);
    }

    for (int ch = 0; ch < NCH; ch++) {
        // store (with tf32 rounding) to shared
#pragma unroll
        for (int i = 0; i < 2; i++) {
            int f = tid + i * 256; int r = f >> 2, cc = (f & 3) * 4;
            float4 v = ra[i];
            v.x = tf32_rna(v.x); v.y = tf32_rna(v.y); v.z = tf32_rna(v.z); v.w = tf32_rna(v.w);
            *(float4*)&As[r * 20 + cc] = v;
        }
#pragma unroll
        for (int i = 0; i < NB4; i++) {
            int f = tid + i * 256; int r = f >> 2, cc = (f & 3) * 4;
            float4 v = rb[i];
            v.x = tf32_rna(v.x); v.y = tf32_rna(v.y); v.z = tf32_rna(v.z); v.w = tf32_rna(v.w);
            *(float4*)&Bs[r * 20 + cc] = v;
        }
        __syncthreads();

        // issue next chunk's global loads (overlap with MMA)
        if (ch + 1 < NCH) {
            int ko = (ch + 1) * 16;
#pragma unroll
            for (int i = 0; i < 2; i++) {
                int f = tid + i * 256; int r = f >> 2, cc = (f & 3) * 4;
                ra[i] = *(const float4*)(Aba + (size_t)r * sA + ko + cc);
            }
#pragma unroll
            for (int i = 0; i < NB4; i++) {
                int f = tid + i * 256; int r = f >> 2, cc = (f & 3) * 4;
                rb[i] = *(const float4*)(Bba + (size_t)r * sB + ko + cc);
            }
        }

        // MMA over the 16-wide chunk (two k=8 sub-steps)
#pragma unroll
        for (int kk = 0; kk < 2; kk++) {
            const int ko = kk * 8;
            float a[2][4];
#pragma unroll
            for (int mf = 0; mf < 2; mf++) {
                int r0 = wm * 32 + mf * 16 + (lane >> 2);
                a[mf][0] = As[r0 * 20 + ko + (lane & 3)];
                a[mf][1] = As[(r0 + 8) * 20 + ko + (lane & 3)];
                a[mf][2] = As[r0 * 20 + ko + 4 + (lane & 3)];
                a[mf][3] = As[(r0 + 8) * 20 + ko + 4 + (lane & 3)];
            }
            float b[NF][2];
#pragma unroll
            for (int nf = 0; nf < NF; nf++) {
                int rr = wn * (TN / 2) + nf * 8 + (lane >> 2);
                b[nf][0] = Bs[rr * 20 + ko + (lane & 3)];
                b[nf][1] = Bs[rr * 20 + ko + 4 + (lane & 3)];
            }
#pragma unroll
            for (int mf = 0; mf < 2; mf++)
#pragma unroll
                for (int nf = 0; nf < NF; nf++)
                    mma_tf32(c[mf][nf], a[mf], b[nf]);
        }
        __syncthreads();
    }

    // ---------------- epilogue ----------------
#pragma unroll
    for (int mf = 0; mf < 2; mf++) {
#pragma unroll
        for (int nf = 0; nf < NF; nf++) {
            int rib0 = wm * 32 + mf * 16 + (lane >> 2);
            int cib = wn * (TN / 2) + nf * 8 + 2 * (lane & 3);
#pragma unroll
            for (int e = 0; e < 2; e++) {
                int rib = rib0 + e * 8;
                float v0 = c[mf][nf][e * 2], v1 = c[mf][nf][e * 2 + 1];
                if (MODE == 0) {
                    int colg = blockIdx.x * 128 + cib;
                    int rowg = blockIdx.y * 128 + rib;
                    int b = rowg >> 8, n = rowg & 255;
                    int which = colg / 768;
                    int rr = colg - which * 768;
                    int h = rr >> 6, dd = rr & 63;
                    v0 += Xtra[colg]; v1 += Xtra[colg + 1];
                    if (which == 0)
                        *(float2*)&g_qin[(((size_t)(b * 12 + h) * 256) + n) * 64 + dd] = make_float2(v0, v1);
                    else if (which == 1)
                        *(float2*)&g_kin[(((size_t)(b * 12 + h) * 256) + n) * 64 + dd] = make_float2(v0, v1);
                    else {
                        g_vt[(((size_t)(b * 12 + h)) * 64 + dd) * 256 + n] = v0;
                        g_vt[(((size_t)(b * 12 + h)) * 64 + dd + 1) * 256 + n] = v1;
                    }
                } else if (MODE == 1) {
                    float gs = Xtra[0];
                    int b = blockIdx.z, h = blockIdx.y;
                    int nt = blockIdx.x >> 1, mt = blockIdx.x & 1;
                    int n = nt * 128 + rib;
                    int m = mt * 128 + cib;
                    v0 = v0 * v0 * gs; v1 = v1 * v1 * gs;
                    *(float2*)&g_sq[(((size_t)(b * 12 + h) * 256) + n) * 256 + m] = make_float2(v0, v1);
                } else if (MODE == 2) {
                    int bh = blockIdx.y; int b = bh / 12, h = bh - b * 12;
                    int n = blockIdx.x * 128 + rib;
                    *(float2*)&g_ctx[((size_t)(b * 256 + n)) * 768 + h * 64 + cib] = make_float2(v0, v1);
                } else {
                    int colg = blockIdx.x * 128 + cib;
                    int rowg = blockIdx.y * 128 + rib;
                    v0 += Xtra[colg]; v1 += Xtra[colg + 1];
                    *(float2*)&Og[(size_t)rowg * 768 + colg] = make_float2(v0, v1);
                }
            }
        }
    }
}

// =====================================================================
// Batched Householder QR (LAPACK sgeqrf + sorg2r convention).
// NEW trailing update: all-threads phases (rowgroup x column) instead of
// warp-per-column — same FLOPs, ~8x shorter dependency chains.
// One block per slab (768 slabs: 384 q + 384 k). Slab is 256x64.
// =====================================================================
__global__ void __launch_bounds__(256) qr_kernel()
{
    extern __shared__ float sA[];   // 64 * 257
    __shared__ float s_tau[64];
    __shared__ float s_red[8];
    __shared__ float s_dt[4][64];

    const int tid = threadIdx.x;
    const int lane = tid & 31, warp = tid >> 5;
    const int cix = tid & 63;       // column handled in update phases
    const int rg  = tid >> 6;       // row group (64 rows each)
    const int r0  = rg * 64;

    int slab = blockIdx.x;
    int isk = (slab >= 384) ? 1 : 0;
    int s = slab - isk * 384;
    const float* src = (isk ? g_kin : g_qin) + (size_t)s * NN * DD;
    float* dst = isk ? g_kgr : g_qgr;
    int b = s / 12, h = s % 12;

    for (int idx = tid; idx < NN * DD; idx += 256) {
        int r = idx >> 6, c = idx & 63;
        sA[c * 257 + r] = src[idx];
    }
    __syncthreads();

    // ---------------- geqrf ----------------
    for (int j = 0; j < 64; j++) {
        float* colj = sA + j * 257;
        // norm partials + alpha (both read BEFORE any write to colj)
        float x = (tid >= j) ? colj[tid] : 0.f;
        float alpha = colj[j];
        float ss = x * x;
#pragma unroll
        for (int o = 16; o > 0; o >>= 1) ss += __shfl_xor_sync(0xffffffffu, ss, o);
        if (lane == 0) s_red[warp] = ss;
        __syncthreads();
        float tot = 0.f;
#pragma unroll
        for (int w = 0; w < 8; w++) tot += s_red[w];
        float norm = sqrtf(tot);
        float tau, scal;
        if (norm < 1e-30f) { tau = 0.f; scal = 0.f; }
        else {
            float beta = (alpha >= 0.f) ? -norm : norm;
            tau = (beta - alpha) / beta;
            scal = 1.f / (alpha - beta);
        }
        if (tid == 0) s_tau[j] = tau;
        // scale col j into v (v_j = 1); alpha/x already consumed
        if (tid > j)       colj[tid] *= scal;
        else if (tid == j) colj[tid] = 1.f;
        __syncthreads();

        // phase 1: partial dots dt[rg][c] = sum_{r in rg, r>=j} v[r]*A[r,c]
        float acc = 0.f;
        if (cix > j) {
            const float* colc = sA + cix * 257;
#pragma unroll 8
            for (int rr = 0; rr < 64; rr++) {
                int r = r0 + rr;
                float vj = colj[r];
                float vc = colc[r];
                if (r >= j) acc += vj * vc;
            }
        }
        s_dt[rg][cix] = acc;
        __syncthreads();

        // phase 2: axpy with w = tau * (sum of 4 partials)
        if (cix > j) {
            float w = tau * (s_dt[0][cix] + s_dt[1][cix] + s_dt[2][cix] + s_dt[3][cix]);
            float* colc = sA + cix * 257;
#pragma unroll 8
            for (int rr = 0; rr < 64; rr++) {
                int r = r0 + rr;
                if (r >= j) colc[r] -= w * colj[r];
            }
        }
        __syncthreads();
    }

    // ---------------- org2r (in place) ----------------
    for (int i = 63; i >= 0; i--) {
        float* coli = sA + i * 257;
        float tau = s_tau[i];

        // phase 1: partial dots for trailing columns (v = coli, v_i = 1 stored)
        float acc = 0.f;
        if (cix > i) {
            const float* colc = sA + cix * 257;
#pragma unroll 8
            for (int rr = 0; rr < 64; rr++) {
                int r = r0 + rr;
                float vi = coli[r];
                float vc = colc[r];
                if (r >= i) acc += vi * vc;
            }
        }
        s_dt[rg][cix] = acc;
        __syncthreads();

        // phase 2: axpy
        if (cix > i) {
            float w = tau * (s_dt[0][cix] + s_dt[1][cix] + s_dt[2][cix] + s_dt[3][cix]);
            float* colc = sA + cix * 257;
#pragma unroll 8
            for (int rr = 0; rr < 64; rr++) {
                int r = r0 + rr;
                if (r >= i) colc[r] -= w * coli[r];
            }
        }
        __syncthreads();

        // rewrite col i as the Q column
        float v = coli[tid];
        float nv;
        if (tid < i)       nv = 0.f;
        else if (tid == i) nv = 1.f - tau;
        else               nv = -tau * v;
        coli[tid] = nv;
        __syncthreads();
    }

    // writeout to (b, n, h*64 + d)
    for (int idx = tid; idx < NN * DD; idx += 256) {
        int r = idx >> 6, c = idx & 63;
        dst[(size_t)(b * 256 + r) * 768 + h * 64 + c] = sA[c * 257 + r];
    }
}

// =====================================================================
// Fused channel-mix + softmax. Block handles (b, 2 n-rows), 512 threads.
// =====================================================================
__global__ void __launch_bounds__(512) mixsoftmax_kernel(const float* __restrict__ conv_w,
                                                         const float* __restrict__ conv_b)
{
    __shared__ float sm[24][260];
    __shared__ float s_w2[12][12];
    __shared__ float s_cb[12];

    int tid = threadIdx.x;
    int b = blockIdx.y;
    int n0 = blockIdx.x * 2;

    if (tid < 144) {
        int o = tid / 12, h = tid % 12;
        s_w2[o][h] = conv_w[o * 24 + h] + conv_w[o * 24 + 12 + h];
    }
    if (tid < 12) s_cb[tid] = conv_b[tid];
    __syncthreads();

    {
        int nn = tid >> 8, m = tid & 255;
        float v[12];
#pragma unroll
        for (int h = 0; h < 12; h++)
            v[h] = g_sq[(((size_t)(b * 12 + h) * 256) + n0 + nn) * 256 + m];
#pragma unroll
        for (int o = 0; o < 12; o++) {
            float acc = s_cb[o];
#pragma unroll
            for (int h = 0; h < 12; h++) acc += s_w2[o][h] * v[h];
            sm[nn * 12 + o][m] = acc;
        }
    }
    __syncthreads();

    int warp = tid >> 5, lane = tid & 31;
    for (int row = warp; row < 24; row += 16) {
        int nn = row / 12, o = row - nn * 12;
        const float* src = sm[row];
        float v[8];
        float mx = -1e30f;
#pragma unroll
        for (int i = 0; i < 8; i++) { v[i] = src[i * 32 + lane]; mx = fmaxf(mx, v[i]); }
#pragma unroll
        for (int off = 16; off > 0; off >>= 1) mx = fmaxf(mx, __shfl_xor_sync(0xffffffffu, mx, off));
        float smv = 0.f;
#pragma unroll
        for (int i = 0; i < 8; i++) { v[i] = expf(v[i] - mx); smv += v[i]; }
#pragma unroll
        for (int off = 16; off > 0; off >>= 1) smv += __shfl_xor_sync(0xffffffffu, smv, off);
        float inv = 1.f / smv;
        float* dstp = g_mix + (((size_t)(b * 12 + o) * 256) + n0 + nn) * 256;
#pragma unroll
        for (int i = 0; i < 8; i++) dstp[i * 32 + lane] = v[i] * inv;
    }
}

// =====================================================================
extern "C" void kernel_launch(void* const* d_in, const int* in_sizes, int n_in,
                              void* d_out, int out_size)
{
    const float* x      = (const float*)d_in[0];
    const float* qkv_w  = (const float*)d_in[1];
    const float* qkv_b  = (const float*)d_in[2];
    const float* gscale = (const float*)d_in[3];
    const float* conv_w = (const float*)d_in[4];
    const float* conv_b = (const float*)d_in[5];
    const float* proj_w = (const float*)d_in[6];
    const float* proj_b = (const float*)d_in[7];
    float* out = (float*)d_out;

    cudaFuncSetAttribute(qr_kernel, cudaFuncAttributeMaxDynamicSharedMemorySize, 64 * 257 * 4);

    // 1) QKV projection + scatter  (M=8192, N=2304, K=768)
    gemm_mma<0, 128, 48><<<dim3(18, 64), 256>>>(x, qkv_w, qkv_b, nullptr);
    // 2) batched Householder QR (768 slabs of 256x64)
    qr_kernel<<<768, 256, 64 * 257 * 4>>>();
    // 3) Grassmann dots, squared+scaled  (per (b,h): 256x256x64)
    gemm_mma<1, 128, 4><<<dim3(4, 12, 32), 256>>>(nullptr, nullptr, gscale, nullptr);
    // 4) channel mix + softmax
    mixsoftmax_kernel<<<dim3(128, 32), 512>>>(conv_w, conv_b);
    // 5) PV  (per (b,h): 256x64x256)
    gemm_mma<2, 64, 16><<<dim3(2, 384), 256>>>(nullptr, nullptr, nullptr, nullptr);
    // 6) output projection (M=8192, N=768, K=768)
    gemm_mma<3, 128, 48><<<dim3(6, 64), 256>>>(nullptr, proj_w, proj_b, out);
}

// round 11
// speedup vs baseline: 1.1845x; 1.1845x over previous
#include <cuda_runtime.h>
#include <cstdint>
#include <math.h>

#define BB 32
#define NN 256
#define HH 12
#define DD 64
#define CC 768

// ---------------- scratch (device globals; no runtime allocation) ----------------
__device__ float g_qin[BB*HH*NN*DD];      // (b,h,n,d)
__device__ float g_kin[BB*HH*NN*DD];      // (b,h,n,d)
__device__ float g_vt [BB*HH*DD*NN];      // (b,h,d,m)  V^T for PV GEMM
__device__ float g_qgr[BB*NN*CC];         // (b,n,h*64+d)
__device__ float g_kgr[BB*NN*CC];         // (b,n,h*64+d)
__device__ float g_sq [(size_t)BB*HH*NN*NN]; // gs*dots^2  (b,h,n,m)
__device__ float g_mix[(size_t)BB*HH*NN*NN]; // softmaxed P (b,o,n,m)
__device__ float g_ctx[BB*NN*CC];         // (b,n,h*64+d)

__device__ __forceinline__ float tf32_rna(float f) {
    uint32_t o;
    asm("cvt.rna.tf32.f32 %0, %1;" : "=r"(o) : "f"(f));
    return __uint_as_float(o);
}

__device__ __forceinline__ void mma_tf32(float* c, const float* a, const float* b) {
    asm volatile(
        "mma.sync.aligned.m16n8k8.row.col.f32.tf32.tf32.f32 "
        "{%0,%1,%2,%3}, {%4,%5,%6,%7}, {%8,%9}, {%0,%1,%2,%3};"
        : "+f"(c[0]), "+f"(c[1]), "+f"(c[2]), "+f"(c[3])
        : "r"(__float_as_uint(a[0])), "r"(__float_as_uint(a[1])),
          "r"(__float_as_uint(a[2])), "r"(__float_as_uint(a[3])),
          "r"(__float_as_uint(b[0])), "r"(__float_as_uint(b[1])));
}

// ======================= TF32 mma.sync GEMM (R3 structure — proven fast) =======================
// C[M,N] = A[M,K] @ B[N,K]^T. Block tile: 128 x TN, K-chunk 16.
// 8 warps 4(m) x 2(n); warp tile 32 x TN/2.
// MODE 0: qkv = x @ qkv_w^T + b, scatter to q/k/vt
// MODE 1: dots per (b,h); epilogue sq = gs*dots^2
// MODE 2: PV per (b,h): P(256x256) @ Vt(64x256)^T -> ctx
// MODE 3: proj = ctx @ proj_w^T + b -> out
template<int MODE, int TN, int NCH>
__global__ void __launch_bounds__(256) gemm_mma(const float* __restrict__ Ain,
                                                const float* __restrict__ Bin,
                                                const float* __restrict__ Xtra,
                                                float* __restrict__ Og)
{
    __shared__ float As[128 * 20];
    __shared__ float Bs[TN * 20];
    constexpr int NF = TN / 16;            // n-fragments per warp
    constexpr int NB4 = (TN * 4) / 256;    // B float4 loads per thread (2 or 1)

    const int tid = threadIdx.x, lane = tid & 31, wid = tid >> 5;
    const int wm = wid >> 1, wn = wid & 1;

    const float* Aba; const float* Bba; int sA, sB;
    if (MODE == 0) {
        Aba = Ain + (size_t)blockIdx.y * 128 * 768; sA = 768;
        Bba = Bin + (size_t)blockIdx.x * 128 * 768; sB = 768;
    } else if (MODE == 1) {
        int b = blockIdx.z, h = blockIdx.y;
        int nt = blockIdx.x >> 1, mt = blockIdx.x & 1;
        Aba = g_qgr + ((size_t)(b * 256 + nt * 128)) * 768 + h * 64; sA = 768;
        Bba = g_kgr + ((size_t)(b * 256 + mt * 128)) * 768 + h * 64; sB = 768;
    } else if (MODE == 2) {
        Aba = g_mix + (size_t)blockIdx.y * 65536 + (size_t)blockIdx.x * 128 * 256; sA = 256;
        Bba = g_vt + (size_t)blockIdx.y * 16384; sB = 256;
    } else {
        Aba = g_ctx + (size_t)blockIdx.y * 128 * 768; sA = 768;
        Bba = Bin + (size_t)blockIdx.x * 128 * 768; sB = 768;
    }

    float c[2][NF][4];
#pragma unroll
    for (int mf = 0; mf < 2; mf++)
#pragma unroll
        for (int nf = 0; nf < NF; nf++)
#pragma unroll
            for (int e = 0; e < 4; e++) c[mf][nf][e] = 0.f;

    float4 ra[2], rb[NB4];

    // prologue loads
#pragma unroll
    for (int i = 0; i < 2; i++) {
        int f = tid + i * 256; int r = f >> 2, cc = (f & 3) * 4;
        ra[i] = *(const float4*)(Aba + (size_t)r * sA + cc);
    }
#pragma unroll
    for (int i = 0; i < NB4; i++) {
        int f = tid + i * 256; int r = f >> 2, cc = (f & 3) * 4;
        rb[i] = *(const float4*)(Bba + (size_t)r * sB + cc);
    }

    for (int ch = 0; ch < NCH; ch++) {
        // store (with tf32 rounding) to shared
#pragma unroll
        for (int i = 0; i < 2; i++) {
            int f = tid + i * 256; int r = f >> 2, cc = (f & 3) * 4;
            float4 v = ra[i];
            v.x = tf32_rna(v.x); v.y = tf32_rna(v.y); v.z = tf32_rna(v.z); v.w = tf32_rna(v.w);
            *(float4*)&As[r * 20 + cc] = v;
        }
#pragma unroll
        for (int i = 0; i < NB4; i++) {
            int f = tid + i * 256; int r = f >> 2, cc = (f & 3) * 4;
            float4 v = rb[i];
            v.x = tf32_rna(v.x); v.y = tf32_rna(v.y); v.z = tf32_rna(v.z); v.w = tf32_rna(v.w);
            *(float4*)&Bs[r * 20 + cc] = v;
        }
        __syncthreads();

        // issue next chunk's global loads (overlap with MMA)
        if (ch + 1 < NCH) {
            int ko = (ch + 1) * 16;
#pragma unroll
            for (int i = 0; i < 2; i++) {
                int f = tid + i * 256; int r = f >> 2, cc = (f & 3) * 4;
                ra[i] = *(const float4*)(Aba + (size_t)r * sA + ko + cc);
            }
#pragma unroll
            for (int i = 0; i < NB4; i++) {
                int f = tid + i * 256; int r = f >> 2, cc = (f & 3) * 4;
                rb[i] = *(const float4*)(Bba + (size_t)r * sB + ko + cc);
            }
        }

        // MMA over the 16-wide chunk (two k=8 sub-steps)
#pragma unroll
        for (int kk = 0; kk < 2; kk++) {
            const int ko = kk * 8;
            float a[2][4];
#pragma unroll
            for (int mf = 0; mf < 2; mf++) {
                int r0 = wm * 32 + mf * 16 + (lane >> 2);
                a[mf][0] = As[r0 * 20 + ko + (lane & 3)];
                a[mf][1] = As[(r0 + 8) * 20 + ko + (lane & 3)];
                a[mf][2] = As[r0 * 20 + ko + 4 + (lane & 3)];
                a[mf][3] = As[(r0 + 8) * 20 + ko + 4 + (lane & 3)];
            }
            float b[NF][2];
#pragma unroll
            for (int nf = 0; nf < NF; nf++) {
                int rr = wn * (TN / 2) + nf * 8 + (lane >> 2);
                b[nf][0] = Bs[rr * 20 + ko + (lane & 3)];
                b[nf][1] = Bs[rr * 20 + ko + 4 + (lane & 3)];
            }
#pragma unroll
            for (int mf = 0; mf < 2; mf++)
#pragma unroll
                for (int nf = 0; nf < NF; nf++)
                    mma_tf32(c[mf][nf], a[mf], b[nf]);
        }
        __syncthreads();
    }

    // ---------------- epilogue ----------------
#pragma unroll
    for (int mf = 0; mf < 2; mf++) {
#pragma unroll
        for (int nf = 0; nf < NF; nf++) {
            int rib0 = wm * 32 + mf * 16 + (lane >> 2);
            int cib = wn * (TN / 2) + nf * 8 + 2 * (lane & 3);
#pragma unroll
            for (int e = 0; e < 2; e++) {
                int rib = rib0 + e * 8;
                float v0 = c[mf][nf][e * 2], v1 = c[mf][nf][e * 2 + 1];
                if (MODE == 0) {
                    int colg = blockIdx.x * 128 + cib;
                    int rowg = blockIdx.y * 128 + rib;
                    int b = rowg >> 8, n = rowg & 255;
                    int which = colg / 768;
                    int rr = colg - which * 768;
                    int h = rr >> 6, dd = rr & 63;
                    v0 += Xtra[colg]; v1 += Xtra[colg + 1];
                    if (which == 0)
                        *(float2*)&g_qin[(((size_t)(b * 12 + h) * 256) + n) * 64 + dd] = make_float2(v0, v1);
                    else if (which == 1)
                        *(float2*)&g_kin[(((size_t)(b * 12 + h) * 256) + n) * 64 + dd] = make_float2(v0, v1);
                    else {
                        g_vt[(((size_t)(b * 12 + h)) * 64 + dd) * 256 + n] = v0;
                        g_vt[(((size_t)(b * 12 + h)) * 64 + dd + 1) * 256 + n] = v1;
                    }
                } else if (MODE == 1) {
                    float gs = Xtra[0];
                    int b = blockIdx.z, h = blockIdx.y;
                    int nt = blockIdx.x >> 1, mt = blockIdx.x & 1;
                    int n = nt * 128 + rib;
                    int m = mt * 128 + cib;
                    v0 = v0 * v0 * gs; v1 = v1 * v1 * gs;
                    *(float2*)&g_sq[(((size_t)(b * 12 + h) * 256) + n) * 256 + m] = make_float2(v0, v1);
                } else if (MODE == 2) {
                    int bh = blockIdx.y; int b = bh / 12, h = bh - b * 12;
                    int n = blockIdx.x * 128 + rib;
                    *(float2*)&g_ctx[((size_t)(b * 256 + n)) * 768 + h * 64 + cib] = make_float2(v0, v1);
                } else {
                    int colg = blockIdx.x * 128 + cib;
                    int rowg = blockIdx.y * 128 + rib;
                    v0 += Xtra[colg]; v1 += Xtra[colg + 1];
                    *(float2*)&Og[(size_t)rowg * 768 + colg] = make_float2(v0, v1);
                }
            }
        }
    }
}

// =====================================================================
// Batched Householder QR (LAPACK sgeqrf + sorg2r convention).
// R9 structure, but 512 threads / 16 warps: warp-per-column trailing
// update walks HALF as many columns per warp (latency chain halves);
// identical memory pattern & summation order => bit-identical numerics.
// One block per slab (768 slabs: 384 q + 384 k). Slab is 256x64.
// =====================================================================
__global__ void __launch_bounds__(512) qr_kernel()
{
    extern __shared__ float sA[];   // 64 * 257
    __shared__ float s_tau[64];
    __shared__ float s_red[16];

    const int tid = threadIdx.x;
    const int lane = tid & 31, warp = tid >> 5;   // 16 warps

    int slab = blockIdx.x;
    int isk = (slab >= 384) ? 1 : 0;
    int s = slab - isk * 384;
    const float* src = (isk ? g_kin : g_qin) + (size_t)s * NN * DD;
    float* dst = isk ? g_kgr : g_qgr;
    int b = s / 12, h = s % 12;

    for (int idx = tid; idx < NN * DD; idx += 512) {
        int r = idx >> 6, c = idx & 63;
        sA[c * 257 + r] = src[idx];
    }
    __syncthreads();

    // ---------------- geqrf ----------------
    for (int j = 0; j < 64; j++) {
        float* colj = sA + j * 257;
        float x = (tid >= j && tid < 256) ? colj[tid] : 0.f;
        float ss = x * x;
#pragma unroll
        for (int o = 16; o > 0; o >>= 1) ss += __shfl_xor_sync(0xffffffffu, ss, o);
        if (lane == 0) s_red[warp] = ss;
        __syncthreads();
        float tot = 0.f;
#pragma unroll
        for (int w = 0; w < 16; w++) tot += s_red[w];
        float alpha = colj[j];
        float norm = sqrtf(tot);
        float tau, scal;
        if (norm < 1e-30f) { tau = 0.f; scal = 0.f; }
        else {
            float beta = (alpha >= 0.f) ? -norm : norm;
            tau = (beta - alpha) / beta;
            scal = 1.f / (alpha - beta);
        }
        if (tid == 0) s_tau[j] = tau;
        __syncthreads();                 // all reads of colj done before writes
        if (tid < 256) {
            if (tid > j)       colj[tid] *= scal;   // store v (v_j = 1)
            else if (tid == j) colj[tid] = 1.f;
        }
        __syncthreads();
        // trailing update: warp-per-column, 16 warps
        for (int c = j + 1 + warp; c < 64; c += 16) {
            float* colc = sA + c * 257;
            float dt = 0.f;
            for (int r = lane; r < 256; r += 32)
                if (r >= j) dt += colj[r] * colc[r];
#pragma unroll
            for (int o = 16; o > 0; o >>= 1) dt += __shfl_xor_sync(0xffffffffu, dt, o);
            float w = tau * dt;
            for (int r = lane; r < 256; r += 32)
                if (r >= j) colc[r] -= w * colj[r];
        }
        __syncthreads();
    }

    // ---------------- org2r (in place) ----------------
    for (int i = 63; i >= 0; i--) {
        float* coli = sA + i * 257;
        float tau = s_tau[i];
        for (int c = i + 1 + warp; c < 64; c += 16) {
            float* colc = sA + c * 257;
            float dt = 0.f;
            for (int r = lane; r < 256; r += 32)
                if (r >= i) dt += coli[r] * colc[r];
#pragma unroll
            for (int o = 16; o > 0; o >>= 1) dt += __shfl_xor_sync(0xffffffffu, dt, o);
            float w = tau * dt;
            for (int r = lane; r < 256; r += 32)
                if (r >= i) colc[r] -= w * coli[r];
        }
        __syncthreads();
        if (tid < 256) {
            float v = coli[tid];
            float nv;
            if (tid < i)       nv = 0.f;
            else if (tid == i) nv = 1.f - tau;
            else               nv = -tau * v;
            coli[tid] = nv;
        }
        __syncthreads();
    }

    // writeout to (b, n, h*64 + d)
    for (int idx = tid; idx < NN * DD; idx += 512) {
        int r = idx >> 6, c = idx & 63;
        dst[(size_t)(b * 256 + r) * 768 + h * 64 + c] = sA[c * 257 + r];
    }
}

// =====================================================================
// Fused channel-mix + softmax. Block handles (b, 2 n-rows), 512 threads.
// =====================================================================
__global__ void __launch_bounds__(512) mixsoftmax_kernel(const float* __restrict__ conv_w,
                                                         const float* __restrict__ conv_b)
{
    __shared__ float sm[24][260];
    __shared__ float s_w2[12][12];
    __shared__ float s_cb[12];

    int tid = threadIdx.x;
    int b = blockIdx.y;
    int n0 = blockIdx.x * 2;

    if (tid < 144) {
        int o = tid / 12, h = tid % 12;
        s_w2[o][h] = conv_w[o * 24 + h] + conv_w[o * 24 + 12 + h];
    }
    if (tid < 12) s_cb[tid] = conv_b[tid];
    __syncthreads();

    {
        int nn = tid >> 8, m = tid & 255;
        float v[12];
#pragma unroll
        for (int h = 0; h < 12; h++)
            v[h] = g_sq[(((size_t)(b * 12 + h) * 256) + n0 + nn) * 256 + m];
#pragma unroll
        for (int o = 0; o < 12; o++) {
            float acc = s_cb[o];
#pragma unroll
            for (int h = 0; h < 12; h++) acc += s_w2[o][h] * v[h];
            sm[nn * 12 + o][m] = acc;
        }
    }
    __syncthreads();

    int warp = tid >> 5, lane = tid & 31;
    for (int row = warp; row < 24; row += 16) {
        int nn = row / 12, o = row - nn * 12;
        const float* src = sm[row];
        float v[8];
        float mx = -1e30f;
#pragma unroll
        for (int i = 0; i < 8; i++) { v[i] = src[i * 32 + lane]; mx = fmaxf(mx, v[i]); }
#pragma unroll
        for (int off = 16; off > 0; off >>= 1) mx = fmaxf(mx, __shfl_xor_sync(0xffffffffu, mx, off));
        float smv = 0.f;
#pragma unroll
        for (int i = 0; i < 8; i++) { v[i] = expf(v[i] - mx); smv += v[i]; }
#pragma unroll
        for (int off = 16; off > 0; off >>= 1) smv += __shfl_xor_sync(0xffffffffu, smv, off);
        float inv = 1.f / smv;
        float* dstp = g_mix + (((size_t)(b * 12 + o) * 256) + n0 + nn) * 256;
#pragma unroll
        for (int i = 0; i < 8; i++) dstp[i * 32 + lane] = v[i] * inv;
    }
}

// =====================================================================
extern "C" void kernel_launch(void* const* d_in, const int* in_sizes, int n_in,
                              void* d_out, int out_size)
{
    const float* x      = (const float*)d_in[0];
    const float* qkv_w  = (const float*)d_in[1];
    const float* qkv_b  = (const float*)d_in[2];
    const float* gscale = (const float*)d_in[3];
    const float* conv_w = (const float*)d_in[4];
    const float* conv_b = (const float*)d_in[5];
    const float* proj_w = (const float*)d_in[6];
    const float* proj_b = (const float*)d_in[7];
    float* out = (float*)d_out;

    cudaFuncSetAttribute(qr_kernel, cudaFuncAttributeMaxDynamicSharedMemorySize, 64 * 257 * 4);

    // 1) QKV projection + scatter  (M=8192, N=2304, K=768)
    gemm_mma<0, 128, 48><<<dim3(18, 64), 256>>>(x, qkv_w, qkv_b, nullptr);
    // 2) batched Householder QR (768 slabs of 256x64)
    qr_kernel<<<768, 512, 64 * 257 * 4>>>();
    // 3) Grassmann dots, squared+scaled  (per (b,h): 256x256x64)
    gemm_mma<1, 128, 4><<<dim3(4, 12, 32), 256>>>(nullptr, nullptr, gscale, nullptr);
    // 4) channel mix + softmax
    mixsoftmax_kernel<<<dim3(128, 32), 512>>>(conv_w, conv_b);
    // 5) PV  (per (b,h): 256x64x256)
    gemm_mma<2, 64, 16><<<dim3(2, 384), 256>>>(nullptr, nullptr, nullptr, nullptr);
    // 6) output projection (M=8192, N=768, K=768)
    gemm_mma<3, 128, 48><<<dim3(6, 64), 256>>>(nullptr, proj_w, proj_b, out);
}

// round 12
// speedup vs baseline: 1.5253x; 1.2877x over previous
#include <cuda_runtime.h>
#include <cstdint>
#include <math.h>

#define BB 32
#define NN 256
#define HH 12
#define DD 64
#define CC 768

// ---------------- scratch (device globals; no runtime allocation) ----------------
__device__ float g_qin[BB*HH*NN*DD];      // (b,h,n,d)
__device__ float g_kin[BB*HH*NN*DD];      // (b,h,n,d)
__device__ float g_vt [BB*HH*DD*NN];      // (b,h,d,m)  V^T for PV GEMM
__device__ float g_qgr[BB*NN*CC];         // (b,n,h*64+d)
__device__ float g_kgr[BB*NN*CC];         // (b,n,h*64+d)
__device__ float g_sq [(size_t)BB*HH*NN*NN]; // gs*dots^2  (b,h,n,m)
__device__ float g_mix[(size_t)BB*HH*NN*NN]; // softmaxed P (b,o,n,m)
__device__ float g_ctx[BB*NN*CC];         // (b,n,h*64+d)

__device__ __forceinline__ float tf32_rna(float f) {
    uint32_t o;
    asm("cvt.rna.tf32.f32 %0, %1;" : "=r"(o) : "f"(f));
    return __uint_as_float(o);
}

__device__ __forceinline__ void mma_tf32(float* c, const float* a, const float* b) {
    asm volatile(
        "mma.sync.aligned.m16n8k8.row.col.f32.tf32.tf32.f32 "
        "{%0,%1,%2,%3}, {%4,%5,%6,%7}, {%8,%9}, {%0,%1,%2,%3};"
        : "+f"(c[0]), "+f"(c[1]), "+f"(c[2]), "+f"(c[3])
        : "r"(__float_as_uint(a[0])), "r"(__float_as_uint(a[1])),
          "r"(__float_as_uint(a[2])), "r"(__float_as_uint(a[3])),
          "r"(__float_as_uint(b[0])), "r"(__float_as_uint(b[1])));
}

// ======================= TF32 mma.sync GEMM (R3 structure — proven fast) =======================
template<int MODE, int TN, int NCH>
__global__ void __launch_bounds__(256) gemm_mma(const float* __restrict__ Ain,
                                                const float* __restrict__ Bin,
                                                const float* __restrict__ Xtra,
                                                float* __restrict__ Og)
{
    __shared__ float As[128 * 20];
    __shared__ float Bs[TN * 20];
    constexpr int NF = TN / 16;
    constexpr int NB4 = (TN * 4) / 256;

    const int tid = threadIdx.x, lane = tid & 31, wid = tid >> 5;
    const int wm = wid >> 1, wn = wid & 1;

    const float* Aba; const float* Bba; int sA, sB;
    if (MODE == 0) {
        Aba = Ain + (size_t)blockIdx.y * 128 * 768; sA = 768;
        Bba = Bin + (size_t)blockIdx.x * 128 * 768; sB = 768;
    } else if (MODE == 1) {
        int b = blockIdx.z, h = blockIdx.y;
        int nt = blockIdx.x >> 1, mt = blockIdx.x & 1;
        Aba = g_qgr + ((size_t)(b * 256 + nt * 128)) * 768 + h * 64; sA = 768;
        Bba = g_kgr + ((size_t)(b * 256 + mt * 128)) * 768 + h * 64; sB = 768;
    } else if (MODE == 2) {
        Aba = g_mix + (size_t)blockIdx.y * 65536 + (size_t)blockIdx.x * 128 * 256; sA = 256;
        Bba = g_vt + (size_t)blockIdx.y * 16384; sB = 256;
    } else {
        Aba = g_ctx + (size_t)blockIdx.y * 128 * 768; sA = 768;
        Bba = Bin + (size_t)blockIdx.x * 128 * 768; sB = 768;
    }

    float c[2][NF][4];
#pragma unroll
    for (int mf = 0; mf < 2; mf++)
#pragma unroll
        for (int nf = 0; nf < NF; nf++)
#pragma unroll
            for (int e = 0; e < 4; e++) c[mf][nf][e] = 0.f;

    float4 ra[2], rb[NB4];

#pragma unroll
    for (int i = 0; i < 2; i++) {
        int f = tid + i * 256; int r = f >> 2, cc = (f & 3) * 4;
        ra[i] = *(const float4*)(Aba + (size_t)r * sA + cc);
    }
#pragma unroll
    for (int i = 0; i < NB4; i++) {
        int f = tid + i * 256; int r = f >> 2, cc = (f & 3) * 4;
        rb[i] = *(const float4*)(Bba + (size_t)r * sB + cc);
    }

    for (int ch = 0; ch < NCH; ch++) {
#pragma unroll
        for (int i = 0; i < 2; i++) {
            int f = tid + i * 256; int r = f >> 2, cc = (f & 3) * 4;
            float4 v = ra[i];
            v.x = tf32_rna(v.x); v.y = tf32_rna(v.y); v.z = tf32_rna(v.z); v.w = tf32_rna(v.w);
            *(float4*)&As[r * 20 + cc] = v;
        }
#pragma unroll
        for (int i = 0; i < NB4; i++) {
            int f = tid + i * 256; int r = f >> 2, cc = (f & 3) * 4;
            float4 v = rb[i];
            v.x = tf32_rna(v.x); v.y = tf32_rna(v.y); v.z = tf32_rna(v.z); v.w = tf32_rna(v.w);
            *(float4*)&Bs[r * 20 + cc] = v;
        }
        __syncthreads();

        if (ch + 1 < NCH) {
            int ko = (ch + 1) * 16;
#pragma unroll
            for (int i = 0; i < 2; i++) {
                int f = tid + i * 256; int r = f >> 2, cc = (f & 3) * 4;
                ra[i] = *(const float4*)(Aba + (size_t)r * sA + ko + cc);
            }
#pragma unroll
            for (int i = 0; i < NB4; i++) {
                int f = tid + i * 256; int r = f >> 2, cc = (f & 3) * 4;
                rb[i] = *(const float4*)(Bba + (size_t)r * sB + ko + cc);
            }
        }

#pragma unroll
        for (int kk = 0; kk < 2; kk++) {
            const int ko = kk * 8;
            float a[2][4];
#pragma unroll
            for (int mf = 0; mf < 2; mf++) {
                int r0 = wm * 32 + mf * 16 + (lane >> 2);
                a[mf][0] = As[r0 * 20 + ko + (lane & 3)];
                a[mf][1] = As[(r0 + 8) * 20 + ko + (lane & 3)];
                a[mf][2] = As[r0 * 20 + ko + 4 + (lane & 3)];
                a[mf][3] = As[(r0 + 8) * 20 + ko + 4 + (lane & 3)];
            }
            float b[NF][2];
#pragma unroll
            for (int nf = 0; nf < NF; nf++) {
                int rr = wn * (TN / 2) + nf * 8 + (lane >> 2);
                b[nf][0] = Bs[rr * 20 + ko + (lane & 3)];
                b[nf][1] = Bs[rr * 20 + ko + 4 + (lane & 3)];
            }
#pragma unroll
            for (int mf = 0; mf < 2; mf++)
#pragma unroll
                for (int nf = 0; nf < NF; nf++)
                    mma_tf32(c[mf][nf], a[mf], b[nf]);
        }
        __syncthreads();
    }

#pragma unroll
    for (int mf = 0; mf < 2; mf++) {
#pragma unroll
        for (int nf = 0; nf < NF; nf++) {
            int rib0 = wm * 32 + mf * 16 + (lane >> 2);
            int cib = wn * (TN / 2) + nf * 8 + 2 * (lane & 3);
#pragma unroll
            for (int e = 0; e < 2; e++) {
                int rib = rib0 + e * 8;
                float v0 = c[mf][nf][e * 2], v1 = c[mf][nf][e * 2 + 1];
                if (MODE == 0) {
                    int colg = blockIdx.x * 128 + cib;
                    int rowg = blockIdx.y * 128 + rib;
                    int b = rowg >> 8, n = rowg & 255;
                    int which = colg / 768;
                    int rr = colg - which * 768;
                    int h = rr >> 6, dd = rr & 63;
                    v0 += Xtra[colg]; v1 += Xtra[colg + 1];
                    if (which == 0)
                        *(float2*)&g_qin[(((size_t)(b * 12 + h) * 256) + n) * 64 + dd] = make_float2(v0, v1);
                    else if (which == 1)
                        *(float2*)&g_kin[(((size_t)(b * 12 + h) * 256) + n) * 64 + dd] = make_float2(v0, v1);
                    else {
                        g_vt[(((size_t)(b * 12 + h)) * 64 + dd) * 256 + n] = v0;
                        g_vt[(((size_t)(b * 12 + h)) * 64 + dd + 1) * 256 + n] = v1;
                    }
                } else if (MODE == 1) {
                    float gs = Xtra[0];
                    int b = blockIdx.z, h = blockIdx.y;
                    int nt = blockIdx.x >> 1, mt = blockIdx.x & 1;
                    int n = nt * 128 + rib;
                    int m = mt * 128 + cib;
                    v0 = v0 * v0 * gs; v1 = v1 * v1 * gs;
                    *(float2*)&g_sq[(((size_t)(b * 12 + h) * 256) + n) * 256 + m] = make_float2(v0, v1);
                } else if (MODE == 2) {
                    int bh = blockIdx.y; int b = bh / 12, h = bh - b * 12;
                    int n = blockIdx.x * 128 + rib;
                    *(float2*)&g_ctx[((size_t)(b * 256 + n)) * 768 + h * 64 + cib] = make_float2(v0, v1);
                } else {
                    int colg = blockIdx.x * 128 + cib;
                    int rowg = blockIdx.y * 128 + rib;
                    v0 += Xtra[colg]; v1 += Xtra[colg + 1];
                    *(float2*)&Og[(size_t)rowg * 768 + colg] = make_float2(v0, v1);
                }
            }
        }
    }
}

// =====================================================================
// Batched Householder QR — rank-2 (paired reflectors) variant.
// Composite H_{j+1}H_j applied in ONE pass over the trailing block with
// register-cached columns: ~0.4x smem traffic vs single-step.
// LAPACK sgeqrf/sorg2r sign convention preserved exactly.
// =====================================================================
__global__ void __launch_bounds__(256) qr_kernel()
{
    extern __shared__ float sA[];   // 64 * 257
    __shared__ float s_tau[64];
    __shared__ float s_red[8];
    __shared__ float s_red2[8];
    __shared__ float s_alpha, s_vjp;

    const int tid = threadIdx.x;
    const int lane = tid & 31, warp = tid >> 5;

    int slab = blockIdx.x;
    int isk = (slab >= 384) ? 1 : 0;
    int s = slab - isk * 384;
    const float* src = (isk ? g_kin : g_qin) + (size_t)s * NN * DD;
    float* dst = isk ? g_kgr : g_qgr;
    int b = s / 12, h = s % 12;

    for (int idx = tid; idx < NN * DD; idx += 256) {
        int r = idx >> 6, c = idx & 63;
        sA[c * 257 + r] = src[idx];
    }
    __syncthreads();

    // ---------------- geqrf (pairs j, j+1) ----------------
    for (int j = 0; j < 64; j += 2) {
        float* colj  = sA + j * 257;
        float* colj1 = colj + 257;

        // step 1: Householder of col j
        float x = (tid >= j) ? colj[tid] : 0.f;
        float alpha = colj[j];
        float ss = x * x;
#pragma unroll
        for (int o = 16; o > 0; o >>= 1) ss += __shfl_xor_sync(0xffffffffu, ss, o);
        if (lane == 0) s_red[warp] = ss;
        __syncthreads();
        float tot = 0.f;
#pragma unroll
        for (int w = 0; w < 8; w++) tot += s_red[w];
        float norm = sqrtf(tot);
        float tauj, scalj;
        if (norm < 1e-30f) { tauj = 0.f; scalj = 0.f; }
        else {
            float beta = (alpha >= 0.f) ? -norm : norm;
            tauj = (beta - alpha) / beta;
            scalj = 1.f / (alpha - beta);
        }
        if (tid == 0) s_tau[j] = tauj;
        if (tid > j)       colj[tid] = x * scalj;
        else if (tid == j) colj[tid] = 1.f;
        __syncthreads();

        // step 2: apply H_j to col j+1, then Householder of col j+1
        float vj = colj[tid];
        float a1 = colj1[tid];
        float pd = (tid >= j) ? vj * a1 : 0.f;
#pragma unroll
        for (int o = 16; o > 0; o >>= 1) pd += __shfl_xor_sync(0xffffffffu, pd, o);
        if (lane == 0) s_red[warp] = pd;
        __syncthreads();
        float d1 = 0.f;
#pragma unroll
        for (int w = 0; w < 8; w++) d1 += s_red[w];
        float a1n = (tid >= j) ? a1 - tauj * d1 * vj : a1;
        float y  = (tid >= j + 1) ? a1n : 0.f;
        float ss2 = y * y;
        float sv  = (tid >= j + 1) ? vj * a1n : 0.f;
#pragma unroll
        for (int o = 16; o > 0; o >>= 1) {
            ss2 += __shfl_xor_sync(0xffffffffu, ss2, o);
            sv  += __shfl_xor_sync(0xffffffffu, sv, o);
        }
        if (lane == 0) { s_red[warp] = ss2; s_red2[warp] = sv; }
        if (tid == j + 1) { s_alpha = a1n; s_vjp = vj; }
        __syncthreads();
        float tot2 = 0.f, svs = 0.f;
#pragma unroll
        for (int w = 0; w < 8; w++) { tot2 += s_red[w]; svs += s_red2[w]; }
        float alpha2 = s_alpha, vjp = s_vjp;
        float norm2 = sqrtf(tot2);
        float tau1, scal1;
        if (norm2 < 1e-30f) { tau1 = 0.f; scal1 = 0.f; }
        else {
            float beta2 = (alpha2 >= 0.f) ? -norm2 : norm2;
            tau1 = (beta2 - alpha2) / beta2;
            scal1 = 1.f / (alpha2 - beta2);
        }
        if (tid == 0) s_tau[j + 1] = tau1;
        // s12 = v_j . v_{j+1}  (v_{j+1}: 1 at pivot, scaled below)
        float s12 = vjp + scal1 * (svs - vjp * alpha2);
        float nv1;
        if (tid < j + 1)       nv1 = a1n;
        else if (tid == j + 1) nv1 = 1.f;
        else                   nv1 = a1n * scal1;
        colj1[tid] = nv1;
        __syncthreads();

        // step 3: composite rank-2 update of cols j+2..63 (warp-per-column)
        for (int c = j + 2 + warp; c < 64; c += 8) {
            float* colc = sA + c * 257;
            float av[8], vja[8], v1a[8];
            float d1c = 0.f, d2c = 0.f;
#pragma unroll
            for (int k = 0; k < 8; k++) {
                int r = lane + k * 32;
                av[k] = colc[r]; vja[k] = colj[r]; v1a[k] = colj1[r];
                if (r >= j)     d1c += vja[k] * av[k];
                if (r >= j + 1) d2c += v1a[k] * av[k];
            }
#pragma unroll
            for (int o = 16; o > 0; o >>= 1) {
                d1c += __shfl_xor_sync(0xffffffffu, d1c, o);
                d2c += __shfl_xor_sync(0xffffffffu, d2c, o);
            }
            float c1 = tauj * d1c;
            float c2 = tau1 * (d2c - c1 * s12);
#pragma unroll
            for (int k = 0; k < 8; k++) {
                int r = lane + k * 32;
                if (r >= j) {
                    float nv = av[k] - c1 * vja[k];
                    if (r >= j + 1) nv -= c2 * v1a[k];
                    colc[r] = nv;
                }
            }
        }
        __syncthreads();
    }

    // ---------------- org2r (pairs i, i-1) ----------------
    for (int i = 63; i >= 1; i -= 2) {
        float* coli  = sA + i * 257;        // v_i
        float* coli1 = coli - 257;          // v_{i-1}
        float taui = s_tau[i], tau1 = s_tau[i - 1];

        // phase 1 (all threads): s' = v_{i-1}.v_i ; q = Q-col i ; dq = v_{i-1}.q
        int r = tid;
        float vi = coli[r];
        float v1 = coli1[r];
        float sp = (r >= i) ? v1 * vi : 0.f;
        float q;
        if (r < i) q = 0.f; else if (r == i) q = 1.f - taui; else q = -taui * vi;
        float qd = (r >= i) ? v1 * q : 0.f;
#pragma unroll
        for (int o = 16; o > 0; o >>= 1) {
            sp += __shfl_xor_sync(0xffffffffu, sp, o);
            qd += __shfl_xor_sync(0xffffffffu, qd, o);
        }
        if (lane == 0) { s_red[warp] = sp; s_red2[warp] = qd; }
        __syncthreads();
        float s12 = 0.f, dq = 0.f;
#pragma unroll
        for (int w = 0; w < 8; w++) { s12 += s_red[w]; dq += s_red2[w]; }

        // phase 2: composite rank-2 update of cols i+1..63
        for (int c = i + 1 + warp; c < 64; c += 8) {
            float* colc = sA + c * 257;
            float av[8], via[8], v1a[8];
            float di = 0.f, dm = 0.f;
#pragma unroll
            for (int k = 0; k < 8; k++) {
                int rr = lane + k * 32;
                av[k] = colc[rr]; via[k] = coli[rr]; v1a[k] = coli1[rr];
                if (rr >= i)     di += via[k] * av[k];
                if (rr >= i - 1) dm += v1a[k] * av[k];
            }
#pragma unroll
            for (int o = 16; o > 0; o >>= 1) {
                di += __shfl_xor_sync(0xffffffffu, di, o);
                dm += __shfl_xor_sync(0xffffffffu, dm, o);
            }
            float c1 = taui * di;
            float c2 = tau1 * (dm - c1 * s12);
#pragma unroll
            for (int k = 0; k < 8; k++) {
                int rr = lane + k * 32;
                if (rr >= i - 1) {
                    float nv = av[k] - c2 * v1a[k];
                    if (rr >= i) nv -= c1 * via[k];
                    colc[rr] = nv;
                }
            }
        }
        __syncthreads();

        // phase 3: col i = H_{i-1} q ; rewrite col i-1
        float qn = q;
        if (r >= i - 1) qn -= tau1 * dq * v1;
        coli[r] = qn;
        float nv;
        if (r < i - 1)       nv = 0.f;
        else if (r == i - 1) nv = 1.f - tau1;
        else                 nv = -tau1 * v1;
        coli1[r] = nv;
        __syncthreads();
    }

    // writeout to (b, n, h*64 + d)
    for (int idx = tid; idx < NN * DD; idx += 256) {
        int r = idx >> 6, c = idx & 63;
        dst[(size_t)(b * 256 + r) * 768 + h * 64 + c] = sA[c * 257 + r];
    }
}

// =====================================================================
// Fused channel-mix + softmax. Block handles (b, 2 n-rows), 512 threads.
// =====================================================================
__global__ void __launch_bounds__(512) mixsoftmax_kernel(const float* __restrict__ conv_w,
                                                         const float* __restrict__ conv_b)
{
    __shared__ float sm[24][260];
    __shared__ float s_w2[12][12];
    __shared__ float s_cb[12];

    int tid = threadIdx.x;
    int b = blockIdx.y;
    int n0 = blockIdx.x * 2;

    if (tid < 144) {
        int o = tid / 12, h = tid % 12;
        s_w2[o][h] = conv_w[o * 24 + h] + conv_w[o * 24 + 12 + h];
    }
    if (tid < 12) s_cb[tid] = conv_b[tid];
    __syncthreads();

    {
        int nn = tid >> 8, m = tid & 255;
        float v[12];
#pragma unroll
        for (int h = 0; h < 12; h++)
            v[h] = g_sq[(((size_t)(b * 12 + h) * 256) + n0 + nn) * 256 + m];
#pragma unroll
        for (int o = 0; o < 12; o++) {
            float acc = s_cb[o];
#pragma unroll
            for (int h = 0; h < 12; h++) acc += s_w2[o][h] * v[h];
            sm[nn * 12 + o][m] = acc;
        }
    }
    __syncthreads();

    int warp = tid >> 5, lane = tid & 31;
    for (int row = warp; row < 24; row += 16) {
        int nn = row / 12, o = row - nn * 12;
        const float* src = sm[row];
        float v[8];
        float mx = -1e30f;
#pragma unroll
        for (int i = 0; i < 8; i++) { v[i] = src[i * 32 + lane]; mx = fmaxf(mx, v[i]); }
#pragma unroll
        for (int off = 16; off > 0; off >>= 1) mx = fmaxf(mx, __shfl_xor_sync(0xffffffffu, mx, off));
        float smv = 0.f;
#pragma unroll
        for (int i = 0; i < 8; i++) { v[i] = expf(v[i] - mx); smv += v[i]; }
#pragma unroll
        for (int off = 16; off > 0; off >>= 1) smv += __shfl_xor_sync(0xffffffffu, smv, off);
        float inv = 1.f / smv;
        float* dstp = g_mix + (((size_t)(b * 12 + o) * 256) + n0 + nn) * 256;
#pragma unroll
        for (int i = 0; i < 8; i++) dstp[i * 32 + lane] = v[i] * inv;
    }
}

// =====================================================================
extern "C" void kernel_launch(void* const* d_in, const int* in_sizes, int n_in,
                              void* d_out, int out_size)
{
    const float* x      = (const float*)d_in[0];
    const float* qkv_w  = (const float*)d_in[1];
    const float* qkv_b  = (const float*)d_in[2];
    const float* gscale = (const float*)d_in[3];
    const float* conv_w = (const float*)d_in[4];
    const float* conv_b = (const float*)d_in[5];
    const float* proj_w = (const float*)d_in[6];
    const float* proj_b = (const float*)d_in[7];
    float* out = (float*)d_out;

    cudaFuncSetAttribute(qr_kernel, cudaFuncAttributeMaxDynamicSharedMemorySize, 64 * 257 * 4);

    // 1) QKV projection + scatter  (M=8192, N=2304, K=768)
    gemm_mma<0, 128, 48><<<dim3(18, 64), 256>>>(x, qkv_w, qkv_b, nullptr);
    // 2) batched Householder QR (768 slabs of 256x64), rank-2 pairs
    qr_kernel<<<768, 256, 64 * 257 * 4>>>();
    // 3) Grassmann dots, squared+scaled  (per (b,h): 256x256x64)
    gemm_mma<1, 128, 4><<<dim3(4, 12, 32), 256>>>(nullptr, nullptr, gscale, nullptr);
    // 4) channel mix + softmax
    mixsoftmax_kernel<<<dim3(128, 32), 512>>>(conv_w, conv_b);
    // 5) PV  (per (b,h): 256x64x256)
    gemm_mma<2, 64, 16><<<dim3(2, 384), 256>>>(nullptr, nullptr, nullptr, nullptr);
    // 6) output projection (M=8192, N=768, K=768)
    gemm_mma<3, 128, 48><<<dim3(6, 64), 256>>>(nullptr, proj_w, proj_b, out);
}